// round 11
// baseline (speedup 1.0000x reference)
#include <cuda_runtime.h>
#include <math.h>

#define NN     576
#define MR     144
#define RD     15
#define EDGES  (MR * RD)        // 2160
#define BATCH  256
#define ITERS  3
#define CWPB   2                // codewords per block
#define TPC    288              // threads per codeword (2 per check row)
#define TPB    (CWPB * TPC)     // 576
#define HEDGE  8                // max edges per half-thread (8 + 7)
#define MAXDEG 18               // column-degree bound

// Per-codeword shared layout (bytes)
#define E_OFF   0
#define E_SZ    (MAXDEG * NN * 4)            // 41472
#define V_OFF   (E_OFF + E_SZ)               // 41472
#define V_SZ    (NN * 4)                     // 2304
#define CW_SZ   (V_OFF + V_SZ)               // 43776
#define SMEM_BYTES (CWPB * CW_SZ)            // 87552

// Graph structure, fully precomputed by prep (no cross-block dependencies):
__device__ int g_cols[EDGES];    // row-major: column index of edge (m, pos)
__device__ int g_q[MR * NN];     // (m, c) -> slot rank of that edge within column c
__device__ int g_deg[NN];        // column degrees

// Prep: 288 blocks, two independent roles.
//  bid <  144 : row role  — ballot-compact row bid's set columns into g_cols.
//  bid >= 144 : col role  — 4 columns, assign per-column slot ranks via SHARED
//               counters (zeroed locally every run -> deterministic, graph-safe).
__global__ void ldpc_prep(const float* __restrict__ H) {
    const int t = threadIdx.x;

    if (blockIdx.x < MR) {
        // ---- row role ----
        __shared__ int woff[18];
        const int m = blockIdx.x;
        const int w = t >> 5, l = t & 31;

        const float v = H[m * NN + t];
        const unsigned mask = __ballot_sync(0xFFFFFFFFu, v == 1.0f);
        if (l == 0) woff[w] = __popc(mask);
        __syncthreads();
        if (w == 0) {
            int orig = (l < 18) ? woff[l] : 0;
            int c = orig;
            #pragma unroll
            for (int off = 1; off < 32; off <<= 1) {
                int x = __shfl_up_sync(0xFFFFFFFFu, c, off);
                if (l >= off) c += x;
            }
            if (l < 18) woff[l] = c - orig;
        }
        __syncthreads();
        if (v == 1.0f) {
            int pos = woff[w] + __popc(mask & ((1u << l) - 1u));
            g_cols[m * RD + pos] = t;
        }
    } else {
        // ---- column role: 4 columns per block ----
        __shared__ int sfill[4];
        const int quad = blockIdx.x - MR;
        const int cl = t / MR;        // 0..3
        const int m  = t - cl * MR;   // 0..143
        const int c  = quad * 4 + cl;

        if (t < 4) sfill[t] = 0;
        __syncthreads();

        const float v = H[m * NN + c];
        if (v == 1.0f) {
            int q = atomicAdd(&sfill[cl], 1);  // any unique rank works
            g_q[m * NN + c] = q;
        }
        __syncthreads();
        if (m == 0) g_deg[c] = sfill[cl];
    }
}

__device__ __forceinline__ void cw_bar(int half) {
    asm volatile("bar.sync %0, %1;" :: "r"(half + 1), "r"(TPC) : "memory");
}

// Decode: one block = TWO independent codewords (576 threads, 288 each).
// 2 threads per check row (8/7 edge split, 3-value shfl merge), 2 owned
// columns per thread. ONE setup barrier; 2 barriers/iter; no atomics.
__global__ __launch_bounds__(TPB, 1)
void ldpc_decode_kernel(const float* __restrict__ r,
                        const float* __restrict__ alpha,
                        const float* __restrict__ beta,
                        float* __restrict__ out) {
    extern __shared__ char sm[];

    const int t    = threadIdx.x;
    const int half = t / TPC;             // codeword slot in this block
    const int u    = t - half * TPC;      // 0..287 within codeword
    const int row  = u >> 1;              // 0..143
    const int hf   = u & 1;               // edge-split half
    const int b    = blockIdx.x * CWPB + half;

    float* E_sh = (float*)(sm + half * CW_SZ + E_OFF);
    float* V    = (float*)(sm + half * CW_SZ + V_OFF);

    float a_[ITERS], bt_[ITERS];
    #pragma unroll
    for (int it = 0; it < ITERS; it++) { a_[it] = alpha[it]; bt_[it] = beta[it]; }

    // Owned columns: n0 = u, n1 = u + 288 (coalesced within the codeword).
    const int n0 = u, n1 = u + TPC;
    const float rc0 = r[b * NN + n0];
    const float rc1 = r[b * NN + n1];
    V[n0] = rc0;  V[n1] = rc1;

    const int cd0 = g_deg[n0], cd1 = g_deg[n1];

    // This half's edges. cols first (independent loads), then dependent q loads.
    const int j0 = hf * HEDGE;                 // 0 or 8
    const int ne = hf ? (RD - HEDGE) : HEDGE;  // 7 or 8
    int cols[HEDGE], slot[HEDGE];
    #pragma unroll
    for (int jj = 0; jj < HEDGE; jj++)
        cols[jj] = (jj < ne) ? g_cols[row * RD + j0 + jj] : 0;
    #pragma unroll
    for (int jj = 0; jj < HEDGE; jj++)
        slot[jj] = (jj < ne) ? (g_q[row * NN + cols[jj]] * NN + cols[jj]) : 0;

    float Eprev[HEDGE];
    #pragma unroll
    for (int jj = 0; jj < HEDGE; jj++) Eprev[jj] = 0.0f;

    cw_bar(half);   // V initialized

    #pragma unroll
    for (int it = 0; it < ITERS; it++) {
        const float a  = a_[it];
        const float bt = bt_[it];

        // ---- row phase (half): gather, sign XOR, min1/min2 over my edges ----
        float am[HEDGE];
        unsigned sb[HEDGE];
        unsigned sgn = 0u;
        #pragma unroll
        for (int jj = 0; jj < HEDGE; jj++) {
            if (jj < ne) {
                float m = V[cols[jj]] - Eprev[jj];
                sb[jj] = __float_as_uint(m) & 0x80000000u;
                sgn   ^= sb[jj];
                am[jj] = fabsf(m);
            } else {
                sb[jj] = 0u;
                am[jj] = INFINITY;
            }
        }
        // two sub-chains of 4 + merge (first-index tie-break)
        float a1 = INFINITY, a2 = INFINITY; int ja = j0;
        #pragma unroll
        for (int jj = 0; jj < 4; jj++) {
            if (am[jj] < a1) { a2 = a1; a1 = am[jj]; ja = j0 + jj; }
            else if (am[jj] < a2) { a2 = am[jj]; }
        }
        float b1 = INFINITY, b2 = INFINITY; int jb = j0 + 4;
        #pragma unroll
        for (int jj = 4; jj < HEDGE; jj++) {
            if (am[jj] < b1) { b2 = b1; b1 = am[jj]; jb = j0 + jj; }
            else if (am[jj] < b2) { b2 = am[jj]; }
        }
        const bool  tA = (a1 <= b1);
        float min1 = tA ? a1 : b1;
        float min2 = tA ? fminf(a2, b1) : fminf(b2, a1);
        int   jmin = tA ? ja : jb;

        // ---- cross-half merge via 3 shfl_xor(1): sign bit packed into jmin ----
        const int js = (jmin << 1) | (int)(sgn >> 31);
        const float o1 = __shfl_xor_sync(0xFFFFFFFFu, min1, 1);
        const float o2 = __shfl_xor_sync(0xFFFFFFFFu, min2, 1);
        const int   ojs = __shfl_xor_sync(0xFFFFFFFFu, js, 1);
        const unsigned sgc = sgn ^ ((unsigned)ojs << 31);
        const bool mine = hf ? (min1 < o1) : (min1 <= o1);   // low index wins ties
        const int   jminc = mine ? jmin : (ojs >> 1);
        const float min1c = mine ? min1 : o1;
        const float min2c = mine ? fminf(min2, o1) : fminf(o2, min1);

        const float mag1 = a * fmaxf(0.0f, min1c - bt);
        const float mag2 = a * fmaxf(0.0f, min2c - bt);

        // ---- emit my edges ----
        #pragma unroll
        for (int jj = 0; jj < HEDGE; jj++) {
            if (jj < ne) {
                float mag = ((j0 + jj) == jminc) ? mag2 : mag1;
                float e = __uint_as_float(__float_as_uint(mag) ^ (sgc ^ sb[jj]));
                Eprev[jj] = e;
                E_sh[slot[jj]] = e;
            }
        }
        cw_bar(half);   // edges published; V reads done

        // ---- column phase: 2 owned columns, conflict-free ----
        float s0 = rc0, s1 = rc1;
        for (int q = 0; q < cd0; q++) s0 += E_sh[q * NN + n0];
        for (int q = 0; q < cd1; q++) s1 += E_sh[q * NN + n1];
        if (it < ITERS - 1) {
            V[n0] = s0;
            V[n1] = s1;
            cw_bar(half);
        } else {
            out[b * NN + n0] = s0;   // coalesced
            out[b * NN + n1] = s1;
        }
    }
}

extern "C" void kernel_launch(void* const* d_in, const int* in_sizes, int n_in,
                              void* d_out, int out_size) {
    const float* r     = (const float*)d_in[0];   // (256, 576)
    const float* H     = (const float*)d_in[1];   // (144, 576)
    const float* alpha = (const float*)d_in[2];   // (3,)
    const float* beta  = (const float*)d_in[3];   // (3,)
    float* out = (float*)d_out;                   // (256, 576)

    cudaFuncSetAttribute(ldpc_decode_kernel,
                         cudaFuncAttributeMaxDynamicSharedMemorySize, SMEM_BYTES);

    ldpc_prep<<<2 * MR, NN>>>(H);
    ldpc_decode_kernel<<<BATCH / CWPB, TPB, SMEM_BYTES>>>(r, alpha, beta, out);
}